// round 14
// baseline (speedup 1.0000x reference)
#include <cuda_runtime.h>
#include <cuda_fp16.h>
#include <cstdint>

#define MTOT 16384
#define EMB  1024
#define LSEQ 2048

// ---------------- scratch (allocation-free rule) ----------------
__device__ __half g_xh[MTOT * EMB];          // fp16 x
__device__ __half g_wqkv[EMB * 3 * EMB];     // fp16 [K][Wq|Wk|Wv] (ldb=3072)
__device__ __half g_wo[EMB * EMB];           // fp16 Wo
__device__ __half g_q[MTOT * EMB];
__device__ __half g_k[MTOT * EMB];
__device__ __half g_v[MTOT * EMB];
__device__ __half g_att[MTOT * EMB];         // scrambled attention output

// ---------------- GEMM config: 128x128 CTA tile, KC=64, 3 stages -----------
#define GKC 64
#define NKT (EMB / GKC)            // 16
#define A_LDH 72                   // halves per A smem row (64 + 8 pad)
#define B_LDH 136                  // halves per B smem row (128 + 8 pad)
#define A_STB (128 * A_LDH * 2)    // 18432
#define B_STB (GKC * B_LDH * 2)    // 17408
#define STG_B (A_STB + B_STB)      // 35840
#define G_SMEM (3 * STG_B)         // 107520

// attn: 4 warps x 2 tokens x 3 tiles x 16x72 halves
#define ATTN_TILE  (16 * 72)
#define ATTN_SMEM  (4 * 2 * 3 * ATTN_TILE * 2)   // 55296

// ---------------- helpers ----------------
__device__ __forceinline__ void cp16(void* s, const void* g) {
    unsigned sa = (unsigned)__cvta_generic_to_shared(s);
    asm volatile("cp.async.cg.shared.global [%0], [%1], 16;\n" :: "r"(sa), "l"(g));
}
__device__ __forceinline__ void cp_commit() {
    asm volatile("cp.async.commit_group;\n" ::);
}
template<int N>
__device__ __forceinline__ void cp_wait() {
    asm volatile("cp.async.wait_group %0;\n" :: "n"(N));
}
__device__ __forceinline__ void ldsm4(uint32_t* r, const __half* p) {
    uint32_t a = (uint32_t)__cvta_generic_to_shared(p);
    asm volatile("ldmatrix.sync.aligned.m8n8.x4.shared.b16 {%0,%1,%2,%3}, [%4];"
        : "=r"(r[0]), "=r"(r[1]), "=r"(r[2]), "=r"(r[3]) : "r"(a));
}
__device__ __forceinline__ void ldsm4t(uint32_t* r, const __half* p) {
    uint32_t a = (uint32_t)__cvta_generic_to_shared(p);
    asm volatile("ldmatrix.sync.aligned.m8n8.x4.trans.shared.b16 {%0,%1,%2,%3}, [%4];"
        : "=r"(r[0]), "=r"(r[1]), "=r"(r[2]), "=r"(r[3]) : "r"(a));
}
__device__ __forceinline__ void ldsm2(uint32_t* r, const __half* p) {
    uint32_t a = (uint32_t)__cvta_generic_to_shared(p);
    asm volatile("ldmatrix.sync.aligned.m8n8.x2.shared.b16 {%0,%1}, [%2];"
        : "=r"(r[0]), "=r"(r[1]) : "r"(a));
}
__device__ __forceinline__ void ldsm2t(uint32_t* r, const __half* p) {
    uint32_t a = (uint32_t)__cvta_generic_to_shared(p);
    asm volatile("ldmatrix.sync.aligned.m8n8.x2.trans.shared.b16 {%0,%1}, [%2];"
        : "=r"(r[0]), "=r"(r[1]) : "r"(a));
}
__device__ __forceinline__ void mma16816(float* c, const uint32_t* a, const uint32_t* b) {
    asm volatile(
        "mma.sync.aligned.m16n8k16.row.col.f32.f16.f16.f32 "
        "{%0,%1,%2,%3}, {%4,%5,%6,%7}, {%8,%9}, {%0,%1,%2,%3};"
        : "+f"(c[0]), "+f"(c[1]), "+f"(c[2]), "+f"(c[3])
        : "r"(a[0]), "r"(a[1]), "r"(a[2]), "r"(a[3]), "r"(b[0]), "r"(b[1]));
}

// ---------------------------------------------------------------------------
// 128x128 raw-mma fp16 GEMM, 128 threads (4 warps of 64x64), 3-stage cp.async,
// 2 CTAs/SM. cp.async issue spread in QUARTERS across all four kk-slices.
// BIAS=false: half output; column block selects among H0/H1/H2 (ldb may be 3072).
// BIAS=true : float output + bias, smem-staged 128B-coalesced stores.
// ---------------------------------------------------------------------------
template<bool BIAS>
__device__ __forceinline__ void gemm_core(
    const __half* __restrict__ A, const __half* __restrict__ B, int ldb,
    __half* __restrict__ H0, __half* __restrict__ H1, __half* __restrict__ H2,
    float* __restrict__ F, const float* __restrict__ bias)
{
    extern __shared__ char smem[];
    const int tid  = threadIdx.x;
    const int warp = tid >> 5;
    const int lane = tid & 31;
    const int bm = blockIdx.y * 128;
    const int bn = blockIdx.x * 128;
    const int wm = (warp >> 1) * 64;
    const int wn = (warp & 1) * 64;

    float c[4][8][4];
#pragma unroll
    for (int i = 0; i < 4; i++)
#pragma unroll
        for (int j = 0; j < 8; j++) {
            c[i][j][0] = 0.f; c[i][j][1] = 0.f; c[i][j][2] = 0.f; c[i][j][3] = 0.f;
        }

    auto issueA = [&](int kt, int h) {      // h in {0,1}: 4 chunks each
        char* st = smem + (kt % 3) * STG_B;
#pragma unroll
        for (int i = h * 4; i < h * 4 + 4; i++) {
            const int idx = tid + i * 128;
            const int row = idx >> 3, cc = idx & 7;
            cp16(st + row * (A_LDH * 2) + cc * 16,
                 A + (size_t)(bm + row) * EMB + kt * GKC + cc * 8);
        }
    };
    auto issueB = [&](int kt, int h) {      // h in {0,1}: 4 chunks; commit at h==1
        char* stb = smem + (kt % 3) * STG_B + A_STB;
#pragma unroll
        for (int i = h * 4; i < h * 4 + 4; i++) {
            const int idx = tid + i * 128;
            const int row = idx >> 4, cc = idx & 15;
            cp16(stb + row * (B_LDH * 2) + cc * 16,
                 B + (size_t)(kt * GKC + row) * ldb + bn + cc * 8);
        }
        if (h == 1) cp_commit();
    };

    issueA(0, 0); issueA(0, 1); issueB(0, 0); issueB(0, 1);
    issueA(1, 0); issueA(1, 1); issueB(1, 0); issueB(1, 1);

    for (int kt = 0; kt < NKT; ++kt) {
        if (kt == NKT - 1) cp_wait<0>(); else cp_wait<1>();
        __syncthreads();

        const __half* sA = (const __half*)(smem + (kt % 3) * STG_B);
        const __half* sB = (const __half*)(smem + (kt % 3) * STG_B + A_STB);
        const bool more = (kt + 2 < NKT);
#pragma unroll
        for (int kk = 0; kk < 4; ++kk) {
            uint32_t a[4][4], b[8][2];
#pragma unroll
            for (int i = 0; i < 4; i++)
                ldsm4(a[i], sA + (wm + i * 16 + (lane & 15)) * A_LDH
                              + kk * 16 + (lane >> 4) * 8);
#pragma unroll
            for (int j2 = 0; j2 < 4; j2++) {
                uint32_t t[4];
                ldsm4t(t, sB + (kk * 16 + (lane & 15)) * B_LDH
                            + wn + j2 * 16 + (lane >> 4) * 8);
                b[2 * j2][0] = t[0]; b[2 * j2][1] = t[1];
                b[2 * j2 + 1][0] = t[2]; b[2 * j2 + 1][1] = t[3];
            }
#pragma unroll
            for (int i = 0; i < 4; i++)
#pragma unroll
                for (int j = 0; j < 8; j++)
                    mma16816(c[i][j], a[i], b[j]);
            // quarter-spread of the next-stage copy across compute slices
            if (more) {
                if (kk == 0) issueA(kt + 2, 0);
                else if (kk == 1) issueA(kt + 2, 1);
                else if (kk == 2) issueB(kt + 2, 0);
                else issueB(kt + 2, 1);
            }
        }
    }

    const int r = lane >> 2, t = lane & 3;
    if (BIAS) {
        // stage fp32 in smem (stride 132, conflict-free), add bias,
        // then fully-coalesced float4 stores
        __syncthreads();
        float* sc = (float*)smem;   // [128][132] floats = 67584 B
#pragma unroll
        for (int i = 0; i < 4; i++)
#pragma unroll
            for (int j = 0; j < 8; j++) {
                const int row0 = wm + i * 16 + r;
                const int col = wn + j * 8 + 2 * t;
                *(float2*)(sc + row0 * 132 + col) = make_float2(c[i][j][0], c[i][j][1]);
                *(float2*)(sc + (row0 + 8) * 132 + col) = make_float2(c[i][j][2], c[i][j][3]);
            }
        __syncthreads();
#pragma unroll
        for (int p = 0; p < 32; p++) {
            const int idx = tid + p * 128;
            const int row = idx >> 5, cf = (idx & 31) * 4;
            const float* sp = sc + row * 132 + cf;
            float4 bb = *(const float4*)(bias + bn + cf);
            float4 v;
            v.x = sp[0] + bb.x; v.y = sp[1] + bb.y;
            v.z = sp[2] + bb.z; v.w = sp[3] + bb.w;
            *(float4*)(F + (size_t)(bm + row) * EMB + bn + cf) = v;
        }
    } else {
        // stage halves in smem, then 16B coalesced stores
        __syncthreads();
        __half* sc = (__half*)smem;   // [128][136] halves
#pragma unroll
        for (int i = 0; i < 4; i++)
#pragma unroll
            for (int j = 0; j < 8; j++) {
                const int row0 = wm + i * 16 + r;
                const int col = wn + j * 8 + 2 * t;
                *(__half2*)(sc + row0 * B_LDH + col) =
                    __floats2half2_rn(c[i][j][0], c[i][j][1]);
                *(__half2*)(sc + (row0 + 8) * B_LDH + col) =
                    __floats2half2_rn(c[i][j][2], c[i][j][3]);
            }
        __syncthreads();
        const int z = bn >> 10;
        __half* O = (z == 0) ? H0 : (z == 1) ? H1 : H2;
        const int bnl = bn & 1023;
#pragma unroll
        for (int i = 0; i < 16; i++) {
            const int idx = tid + i * 128;
            const int row = idx >> 4, cc = idx & 15;
            *(uint4*)(O + (size_t)(bm + row) * EMB + bnl + cc * 8) =
                *(const uint4*)(sc + row * B_LDH + cc * 8);
        }
    }
}

__global__ void __launch_bounds__(128, 2) gemm_qkv_k(
    const __half* __restrict__ A, const __half* __restrict__ W,
    __half* __restrict__ Q, __half* __restrict__ K, __half* __restrict__ V)
{
    gemm_core<false>(A, W, 3 * EMB, Q, K, V, nullptr, nullptr);
}

__global__ void __launch_bounds__(128, 2) gemm_out_k(
    const __half* __restrict__ A, const __half* __restrict__ W,
    float* __restrict__ C, const float* __restrict__ bias)
{
    gemm_core<true>(A, W, EMB, nullptr, nullptr, nullptr, C, bias);
}

// ---------------------------------------------------------------------------
// conversions
// ---------------------------------------------------------------------------
__global__ void __launch_bounds__(256) cvt_f2h(
    const float* __restrict__ in, __half* __restrict__ out, int n8)
{
    const int i = blockIdx.x * blockDim.x + threadIdx.x;
    if (i < n8) {
        float4 a = ((const float4*)in)[2 * i];
        float4 b = ((const float4*)in)[2 * i + 1];
        __half2 h0 = __floats2half2_rn(a.x, a.y);
        __half2 h1 = __floats2half2_rn(a.z, a.w);
        __half2 h2 = __floats2half2_rn(b.x, b.y);
        __half2 h3 = __floats2half2_rn(b.z, b.w);
        uint4 u;
        u.x = *(const unsigned*)&h0; u.y = *(const unsigned*)&h1;
        u.z = *(const unsigned*)&h2; u.w = *(const unsigned*)&h3;
        ((uint4*)out)[i] = u;
    }
}

// all 4 weights in one launch: z<3 -> packed [K][3072] wqkv; z=3 -> wo
__global__ void __launch_bounds__(256) cvt_w4(
    const float* __restrict__ Wq, const float* __restrict__ Wk,
    const float* __restrict__ Wv, const float* __restrict__ Wo,
    __half* __restrict__ wqkv, __half* __restrict__ wo, int n8)
{
    const int z = blockIdx.y;
    const float* in = (z == 0) ? Wq : (z == 1) ? Wk : (z == 2) ? Wv : Wo;
    const int i = blockIdx.x * blockDim.x + threadIdx.x;
    if (i < n8) {
        float4 a = ((const float4*)in)[2 * i];
        float4 b = ((const float4*)in)[2 * i + 1];
        __half2 h0 = __floats2half2_rn(a.x, a.y);
        __half2 h1 = __floats2half2_rn(a.z, a.w);
        __half2 h2 = __floats2half2_rn(b.x, b.y);
        __half2 h3 = __floats2half2_rn(b.z, b.w);
        uint4 u;
        u.x = *(const unsigned*)&h0; u.y = *(const unsigned*)&h1;
        u.z = *(const unsigned*)&h2; u.w = *(const unsigned*)&h3;
        if (z < 3) {
            const int k = i >> 7, cc = i & 127;
            *(uint4*)(wqkv + (size_t)k * (3 * EMB) + z * EMB + cc * 8) = u;
        } else {
            ((uint4*)wo)[i] = u;
        }
    }
}

// ---------------------------------------------------------------------------
// Tensor-core per-token attention: 128 thr, 2 TOKENS PER WARP (8/CTA).
// All 24 uint4 loads issued back-to-back -> doubled MLP.
// ---------------------------------------------------------------------------
__global__ void __launch_bounds__(128) attn_mma(
    const __half* __restrict__ q, const __half* __restrict__ k,
    const __half* __restrict__ v, __half* __restrict__ o)
{
    extern __shared__ __half asmem[];
    const int wid  = threadIdx.x >> 5;
    const int lane = threadIdx.x & 31;
    const int tok0 = blockIdx.x * 8 + wid * 2;

    // load both tokens' Q/K/V tiles; all LDGs issued before any dependent use
#pragma unroll
    for (int tt = 0; tt < 2; tt++) {
        const size_t base = (size_t)(tok0 + tt) * EMB;
        __half* sQ = asmem + (wid * 2 + tt) * 3 * ATTN_TILE;
        __half* sK = sQ + ATTN_TILE;
        __half* sV = sK + ATTN_TILE;
        const uint4* gq = (const uint4*)(q + base);
        const uint4* gk = (const uint4*)(k + base);
        const uint4* gv = (const uint4*)(v + base);
#pragma unroll
        for (int i = 0; i < 4; i++) {
            const int idx = lane + i * 32;
            const int row = idx >> 3, c = idx & 7;
            const int so = row * 72 + c * 8;
            *(uint4*)(sQ + so) = gq[idx];
            *(uint4*)(sK + so) = gk[idx];
            *(uint4*)(sV + so) = gv[idx];
        }
    }
    __syncwarp();

#pragma unroll 1
    for (int tt = 0; tt < 2; tt++) {
        const int tok = tok0 + tt;
        const int n = tok >> 11;
        const int l = tok & 2047;
        __half* sQ = asmem + (wid * 2 + tt) * 3 * ATTN_TILE;
        __half* sK = sQ + ATTN_TILE;
        __half* sV = sK + ATTN_TILE;

        float e0[4] = {0.f, 0.f, 0.f, 0.f};
        float e1[4] = {0.f, 0.f, 0.f, 0.f};
#pragma unroll
        for (int kc = 0; kc < 4; kc++) {
            uint32_t a[4], b0[2], b1[2];
            ldsm4(a, sQ + (lane & 15) * 72 + kc * 16 + (lane >> 4) * 8);
            const int krow = (lane & 7);
            const int koff = kc * 16 + ((lane >> 3) & 1) * 8;
            ldsm2(b0, sK + krow * 72 + koff);
            ldsm2(b1, sK + (8 + krow) * 72 + koff);
            mma16816(e0, a, b0);
            mma16816(e1, a, b1);
        }

        const float scl = 0.03125f;
        float v00 = e0[0] * scl, v01 = e0[1] * scl, v02 = e1[0] * scl, v03 = e1[1] * scl;
        float v10 = e0[2] * scl, v11 = e0[3] * scl, v12 = e1[2] * scl, v13 = e1[3] * scl;
        float m0 = fmaxf(fmaxf(v00, v01), fmaxf(v02, v03));
        float m1 = fmaxf(fmaxf(v10, v11), fmaxf(v12, v13));
        m0 = fmaxf(m0, __shfl_xor_sync(0xffffffffu, m0, 1));
        m0 = fmaxf(m0, __shfl_xor_sync(0xffffffffu, m0, 2));
        m1 = fmaxf(m1, __shfl_xor_sync(0xffffffffu, m1, 1));
        m1 = fmaxf(m1, __shfl_xor_sync(0xffffffffu, m1, 2));
        v00 = __expf(v00 - m0); v01 = __expf(v01 - m0); v02 = __expf(v02 - m0); v03 = __expf(v03 - m0);
        v10 = __expf(v10 - m1); v11 = __expf(v11 - m1); v12 = __expf(v12 - m1); v13 = __expf(v13 - m1);
        float s0 = v00 + v01 + v02 + v03;
        float s1 = v10 + v11 + v12 + v13;
        s0 += __shfl_xor_sync(0xffffffffu, s0, 1); s0 += __shfl_xor_sync(0xffffffffu, s0, 2);
        s1 += __shfl_xor_sync(0xffffffffu, s1, 1); s1 += __shfl_xor_sync(0xffffffffu, s1, 2);
        const float i0 = 1.0f / s0, i1 = 1.0f / s1;

        uint32_t pa[4];
        __half2 h;
        h = __floats2half2_rn(v00 * i0, v01 * i0); pa[0] = *(const uint32_t*)&h;
        h = __floats2half2_rn(v10 * i1, v11 * i1); pa[1] = *(const uint32_t*)&h;
        h = __floats2half2_rn(v02 * i0, v03 * i0); pa[2] = *(const uint32_t*)&h;
        h = __floats2half2_rn(v12 * i1, v13 * i1); pa[3] = *(const uint32_t*)&h;

        const int r  = lane >> 2;
        const int t  = lane & 3;
        const int li = l & 15;
        const int lh = l >> 4;
        const int vrow = (lane & 7) + ((lane >> 3) & 1) * 8;
        const size_t rbase0 = ((size_t)n * LSEQ + r * 128 + lh) * EMB + li * 64;
        const size_t rbase1 = ((size_t)n * LSEQ + (r + 8) * 128 + lh) * EMB + li * 64;
#pragma unroll
        for (int nb = 0; nb < 8; nb++) {
            uint32_t b[2];
            ldsm2t(b, sV + vrow * 72 + nb * 8);
            float c[4] = {0.f, 0.f, 0.f, 0.f};
            mma16816(c, pa, b);
            const int d = nb * 8 + 2 * t;
            __half2 o0 = __floats2half2_rn(c[0], c[1]);
            __half2 o1 = __floats2half2_rn(c[2], c[3]);
            *(__half2*)(o + rbase0 + d) = o0;
            *(__half2*)(o + rbase1 + d) = o1;
        }
    }
}

// ---------------------------------------------------------------------------
extern "C" void kernel_launch(void* const* d_in, const int* in_sizes, int n_in,
                              void* d_out, int out_size)
{
    const float* x  = (const float*)d_in[0];
    const float* Wv = (const float*)d_in[1];
    const float* Wk = (const float*)d_in[2];
    const float* Wq = (const float*)d_in[3];
    const float* Wo = (const float*)d_in[4];
    const float* bo = (const float*)d_in[5];
    float* out = (float*)d_out;

    void *pxh, *pwqkv, *pwo, *pq, *pk, *pv, *pa;
    cudaGetSymbolAddress(&pxh, g_xh);
    cudaGetSymbolAddress(&pwqkv, g_wqkv);
    cudaGetSymbolAddress(&pwo, g_wo);
    cudaGetSymbolAddress(&pq, g_q);
    cudaGetSymbolAddress(&pk, g_k);
    cudaGetSymbolAddress(&pv, g_v);
    cudaGetSymbolAddress(&pa, g_att);
    __half* xh    = (__half*)pxh;
    __half* wqkv  = (__half*)pwqkv;
    __half* wo    = (__half*)pwo;
    __half* qb = (__half*)pq;
    __half* kb = (__half*)pk;
    __half* vb = (__half*)pv;
    __half* ab = (__half*)pa;

    cudaFuncSetAttribute(gemm_qkv_k, cudaFuncAttributeMaxDynamicSharedMemorySize, G_SMEM);
    cudaFuncSetAttribute(gemm_out_k, cudaFuncAttributeMaxDynamicSharedMemorySize, G_SMEM);
    cudaFuncSetAttribute(attn_mma,   cudaFuncAttributeMaxDynamicSharedMemorySize, ATTN_SMEM);

    // 1) conversions
    const int xn8 = MTOT * EMB / 8;
    cvt_f2h<<<(xn8 + 255) / 256, 256>>>(x, xh, xn8);
    const int wn8 = EMB * EMB / 8;
    cvt_w4<<<dim3((wn8 + 255) / 256, 4), 256>>>(Wq, Wk, Wv, Wo, wqkv, wo, wn8);

    // 2) fused QKV projection: [16384,1024] @ [1024,3072]
    gemm_qkv_k<<<dim3(3 * EMB / 128, MTOT / 128), 128, G_SMEM>>>(xh, wqkv, qb, kb, vb);

    // 3) per-token head attention (2 tokens/warp, scrambled fp16 output)
    attn_mma<<<MTOT / 8, 128, ATTN_SMEM>>>(qb, kb, vb, ab);

    // 4) output projection + bias (fp32 out, coalesced staged stores)
    gemm_out_k<<<dim3(EMB / 128, MTOT / 128), 128, G_SMEM>>>(ab, wo, out, bo);
}

// round 15
// speedup vs baseline: 1.0165x; 1.0165x over previous
#include <cuda_runtime.h>
#include <cuda_fp16.h>
#include <cstdint>

#define MTOT 16384
#define EMB  1024
#define LSEQ 2048

// ---------------- scratch (allocation-free rule) ----------------
__device__ __half g_xh[MTOT * EMB];          // fp16 x
__device__ __half g_wqkv[EMB * 3 * EMB];     // fp16 [K][Wq|Wk|Wv] (ldb=3072)
__device__ __half g_wo[EMB * EMB];           // fp16 Wo
__device__ __half g_q[MTOT * EMB];
__device__ __half g_k[MTOT * EMB];
__device__ __half g_v[MTOT * EMB];
__device__ __half g_att[MTOT * EMB];         // scrambled attention output

// ---------------- GEMM config: 128x128 CTA tile, KC=64, 3 stages -----------
#define GKC 64
#define NKT (EMB / GKC)            // 16
#define A_LDH 72                   // halves per A smem row (64 + 8 pad)
#define B_LDH 136                  // halves per B smem row (128 + 8 pad)
#define A_STB (128 * A_LDH * 2)    // 18432
#define B_STB (GKC * B_LDH * 2)    // 17408
#define STG_B (A_STB + B_STB)      // 35840
#define G_SMEM (3 * STG_B)         // 107520

// ---------------- helpers ----------------
__device__ __forceinline__ void cp16(void* s, const void* g) {
    unsigned sa = (unsigned)__cvta_generic_to_shared(s);
    asm volatile("cp.async.cg.shared.global [%0], [%1], 16;\n" :: "r"(sa), "l"(g));
}
__device__ __forceinline__ void cp_commit() {
    asm volatile("cp.async.commit_group;\n" ::);
}
template<int N>
__device__ __forceinline__ void cp_wait() {
    asm volatile("cp.async.wait_group %0;\n" :: "n"(N));
}
__device__ __forceinline__ void ldsm4(uint32_t* r, const __half* p) {
    uint32_t a = (uint32_t)__cvta_generic_to_shared(p);
    asm volatile("ldmatrix.sync.aligned.m8n8.x4.shared.b16 {%0,%1,%2,%3}, [%4];"
        : "=r"(r[0]), "=r"(r[1]), "=r"(r[2]), "=r"(r[3]) : "r"(a));
}
__device__ __forceinline__ void ldsm4t(uint32_t* r, const __half* p) {
    uint32_t a = (uint32_t)__cvta_generic_to_shared(p);
    asm volatile("ldmatrix.sync.aligned.m8n8.x4.trans.shared.b16 {%0,%1,%2,%3}, [%4];"
        : "=r"(r[0]), "=r"(r[1]), "=r"(r[2]), "=r"(r[3]) : "r"(a));
}
__device__ __forceinline__ void ldsm2(uint32_t* r, const __half* p) {
    uint32_t a = (uint32_t)__cvta_generic_to_shared(p);
    asm volatile("ldmatrix.sync.aligned.m8n8.x2.shared.b16 {%0,%1}, [%2];"
        : "=r"(r[0]), "=r"(r[1]) : "r"(a));
}
__device__ __forceinline__ void ldsm2t(uint32_t* r, const __half* p) {
    uint32_t a = (uint32_t)__cvta_generic_to_shared(p);
    asm volatile("ldmatrix.sync.aligned.m8n8.x2.trans.shared.b16 {%0,%1}, [%2];"
        : "=r"(r[0]), "=r"(r[1]) : "r"(a));
}
__device__ __forceinline__ void mma16816(float* c, const uint32_t* a, const uint32_t* b) {
    asm volatile(
        "mma.sync.aligned.m16n8k16.row.col.f32.f16.f16.f32 "
        "{%0,%1,%2,%3}, {%4,%5,%6,%7}, {%8,%9}, {%0,%1,%2,%3};"
        : "+f"(c[0]), "+f"(c[1]), "+f"(c[2]), "+f"(c[3])
        : "r"(a[0]), "r"(a[1]), "r"(a[2]), "r"(a[3]), "r"(b[0]), "r"(b[1]));
}

// ---------------------------------------------------------------------------
// 128x128 raw-mma fp16 GEMM, 128 threads (4 warps of 64x64), 3-stage cp.async,
// 2 CTAs/SM. cp.async issue spread in QUARTERS across all four kk-slices
// (proven in R14: saves ~5us vs half-spread).
// BIAS=false: half output; column block selects among H0/H1/H2 (ldb may be 3072).
// BIAS=true : float output + bias, smem-staged 128B-coalesced stores.
// ---------------------------------------------------------------------------
template<bool BIAS>
__device__ __forceinline__ void gemm_core(
    const __half* __restrict__ A, const __half* __restrict__ B, int ldb,
    __half* __restrict__ H0, __half* __restrict__ H1, __half* __restrict__ H2,
    float* __restrict__ F, const float* __restrict__ bias)
{
    extern __shared__ char smem[];
    const int tid  = threadIdx.x;
    const int warp = tid >> 5;
    const int lane = tid & 31;
    const int bm = blockIdx.y * 128;
    const int bn = blockIdx.x * 128;
    const int wm = (warp >> 1) * 64;
    const int wn = (warp & 1) * 64;

    float c[4][8][4];
#pragma unroll
    for (int i = 0; i < 4; i++)
#pragma unroll
        for (int j = 0; j < 8; j++) {
            c[i][j][0] = 0.f; c[i][j][1] = 0.f; c[i][j][2] = 0.f; c[i][j][3] = 0.f;
        }

    auto issueA = [&](int kt, int h) {      // h in {0,1}: 4 chunks each
        char* st = smem + (kt % 3) * STG_B;
#pragma unroll
        for (int i = h * 4; i < h * 4 + 4; i++) {
            const int idx = tid + i * 128;
            const int row = idx >> 3, cc = idx & 7;
            cp16(st + row * (A_LDH * 2) + cc * 16,
                 A + (size_t)(bm + row) * EMB + kt * GKC + cc * 8);
        }
    };
    auto issueB = [&](int kt, int h) {      // h in {0,1}: 4 chunks; commit at h==1
        char* stb = smem + (kt % 3) * STG_B + A_STB;
#pragma unroll
        for (int i = h * 4; i < h * 4 + 4; i++) {
            const int idx = tid + i * 128;
            const int row = idx >> 4, cc = idx & 15;
            cp16(stb + row * (B_LDH * 2) + cc * 16,
                 B + (size_t)(kt * GKC + row) * ldb + bn + cc * 8);
        }
        if (h == 1) cp_commit();
    };

    issueA(0, 0); issueA(0, 1); issueB(0, 0); issueB(0, 1);
    issueA(1, 0); issueA(1, 1); issueB(1, 0); issueB(1, 1);

    for (int kt = 0; kt < NKT; ++kt) {
        if (kt == NKT - 1) cp_wait<0>(); else cp_wait<1>();
        __syncthreads();

        const __half* sA = (const __half*)(smem + (kt % 3) * STG_B);
        const __half* sB = (const __half*)(smem + (kt % 3) * STG_B + A_STB);
        const bool more = (kt + 2 < NKT);
#pragma unroll
        for (int kk = 0; kk < 4; ++kk) {
            uint32_t a[4][4], b[8][2];
#pragma unroll
            for (int i = 0; i < 4; i++)
                ldsm4(a[i], sA + (wm + i * 16 + (lane & 15)) * A_LDH
                              + kk * 16 + (lane >> 4) * 8);
#pragma unroll
            for (int j2 = 0; j2 < 4; j2++) {
                uint32_t t[4];
                ldsm4t(t, sB + (kk * 16 + (lane & 15)) * B_LDH
                            + wn + j2 * 16 + (lane >> 4) * 8);
                b[2 * j2][0] = t[0]; b[2 * j2][1] = t[1];
                b[2 * j2 + 1][0] = t[2]; b[2 * j2 + 1][1] = t[3];
            }
#pragma unroll
            for (int i = 0; i < 4; i++)
#pragma unroll
                for (int j = 0; j < 8; j++)
                    mma16816(c[i][j], a[i], b[j]);
            // quarter-spread of the next-stage copy across compute slices
            if (more) {
                if (kk == 0) issueA(kt + 2, 0);
                else if (kk == 1) issueA(kt + 2, 1);
                else if (kk == 2) issueB(kt + 2, 0);
                else issueB(kt + 2, 1);
            }
        }
    }

    const int r = lane >> 2, t = lane & 3;
    if (BIAS) {
        // stage fp32 in smem (stride 132, conflict-free), add bias,
        // then fully-coalesced float4 stores
        __syncthreads();
        float* sc = (float*)smem;   // [128][132] floats = 67584 B
#pragma unroll
        for (int i = 0; i < 4; i++)
#pragma unroll
            for (int j = 0; j < 8; j++) {
                const int row0 = wm + i * 16 + r;
                const int col = wn + j * 8 + 2 * t;
                *(float2*)(sc + row0 * 132 + col) = make_float2(c[i][j][0], c[i][j][1]);
                *(float2*)(sc + (row0 + 8) * 132 + col) = make_float2(c[i][j][2], c[i][j][3]);
            }
        __syncthreads();
#pragma unroll
        for (int p = 0; p < 32; p++) {
            const int idx = tid + p * 128;
            const int row = idx >> 5, cf = (idx & 31) * 4;
            const float* sp = sc + row * 132 + cf;
            float4 bb = *(const float4*)(bias + bn + cf);
            float4 v;
            v.x = sp[0] + bb.x; v.y = sp[1] + bb.y;
            v.z = sp[2] + bb.z; v.w = sp[3] + bb.w;
            *(float4*)(F + (size_t)(bm + row) * EMB + bn + cf) = v;
        }
    } else {
        // stage halves in smem, then 16B coalesced stores
        __syncthreads();
        __half* sc = (__half*)smem;   // [128][136] halves
#pragma unroll
        for (int i = 0; i < 4; i++)
#pragma unroll
            for (int j = 0; j < 8; j++) {
                const int row0 = wm + i * 16 + r;
                const int col = wn + j * 8 + 2 * t;
                *(__half2*)(sc + row0 * B_LDH + col) =
                    __floats2half2_rn(c[i][j][0], c[i][j][1]);
                *(__half2*)(sc + (row0 + 8) * B_LDH + col) =
                    __floats2half2_rn(c[i][j][2], c[i][j][3]);
            }
        __syncthreads();
        const int z = bn >> 10;
        __half* O = (z == 0) ? H0 : (z == 1) ? H1 : H2;
        const int bnl = bn & 1023;
#pragma unroll
        for (int i = 0; i < 16; i++) {
            const int idx = tid + i * 128;
            const int row = idx >> 4, cc = idx & 15;
            *(uint4*)(O + (size_t)(bm + row) * EMB + bnl + cc * 8) =
                *(const uint4*)(sc + row * B_LDH + cc * 8);
        }
    }
}

__global__ void __launch_bounds__(128, 2) gemm_qkv_k(
    const __half* __restrict__ A, const __half* __restrict__ W,
    __half* __restrict__ Q, __half* __restrict__ K, __half* __restrict__ V)
{
    gemm_core<false>(A, W, 3 * EMB, Q, K, V, nullptr, nullptr);
}

__global__ void __launch_bounds__(128, 2) gemm_out_k(
    const __half* __restrict__ A, const __half* __restrict__ W,
    float* __restrict__ C, const float* __restrict__ bias)
{
    gemm_core<true>(A, W, EMB, nullptr, nullptr, nullptr, C, bias);
}

// ---------------------------------------------------------------------------
// conversions
// ---------------------------------------------------------------------------
__global__ void __launch_bounds__(256) cvt_f2h(
    const float* __restrict__ in, __half* __restrict__ out, int n8)
{
    const int i = blockIdx.x * blockDim.x + threadIdx.x;
    if (i < n8) {
        float4 a = ((const float4*)in)[2 * i];
        float4 b = ((const float4*)in)[2 * i + 1];
        __half2 h0 = __floats2half2_rn(a.x, a.y);
        __half2 h1 = __floats2half2_rn(a.z, a.w);
        __half2 h2 = __floats2half2_rn(b.x, b.y);
        __half2 h3 = __floats2half2_rn(b.z, b.w);
        uint4 u;
        u.x = *(const unsigned*)&h0; u.y = *(const unsigned*)&h1;
        u.z = *(const unsigned*)&h2; u.w = *(const unsigned*)&h3;
        ((uint4*)out)[i] = u;
    }
}

// all 4 weights in one launch: z<3 -> packed [K][3072] wqkv; z=3 -> wo
__global__ void __launch_bounds__(256) cvt_w4(
    const float* __restrict__ Wq, const float* __restrict__ Wk,
    const float* __restrict__ Wv, const float* __restrict__ Wo,
    __half* __restrict__ wqkv, __half* __restrict__ wo, int n8)
{
    const int z = blockIdx.y;
    const float* in = (z == 0) ? Wq : (z == 1) ? Wk : (z == 2) ? Wv : Wo;
    const int i = blockIdx.x * blockDim.x + threadIdx.x;
    if (i < n8) {
        float4 a = ((const float4*)in)[2 * i];
        float4 b = ((const float4*)in)[2 * i + 1];
        __half2 h0 = __floats2half2_rn(a.x, a.y);
        __half2 h1 = __floats2half2_rn(a.z, a.w);
        __half2 h2 = __floats2half2_rn(b.x, b.y);
        __half2 h3 = __floats2half2_rn(b.z, b.w);
        uint4 u;
        u.x = *(const unsigned*)&h0; u.y = *(const unsigned*)&h1;
        u.z = *(const unsigned*)&h2; u.w = *(const unsigned*)&h3;
        if (z < 3) {
            const int k = i >> 7, cc = i & 127;
            *(uint4*)(wqkv + (size_t)k * (3 * EMB) + z * EMB + cc * 8) = u;
        } else {
            ((uint4*)wo)[i] = u;
        }
    }
}

// ---------------------------------------------------------------------------
// Tensor-core per-token attention (R5/R13 proven: 128 thr, 4 tokens/CTA,
// static smem, 4096 CTAs — best measured 29.8us).
// ---------------------------------------------------------------------------
__global__ void __launch_bounds__(128) attn_mma(
    const __half* __restrict__ q, const __half* __restrict__ k,
    const __half* __restrict__ v, __half* __restrict__ o)
{
    __shared__ __align__(16) __half sm[4][3][16 * 72];
    const int wid  = threadIdx.x >> 5;
    const int lane = threadIdx.x & 31;
    const int tok = blockIdx.x * 4 + wid;
    const int n = tok >> 11;
    const int l = tok & 2047;
    const size_t base = (size_t)tok * EMB;

    __half* sQ = sm[wid][0];
    __half* sK = sm[wid][1];
    __half* sV = sm[wid][2];

    {
        const uint4* gq = (const uint4*)(q + base);
        const uint4* gk = (const uint4*)(k + base);
        const uint4* gv = (const uint4*)(v + base);
#pragma unroll
        for (int i = 0; i < 4; i++) {
            const int idx = lane + i * 32;
            const int row = idx >> 3, c = idx & 7;
            const int so = row * 72 + c * 8;
            *(uint4*)(sQ + so) = gq[idx];
            *(uint4*)(sK + so) = gk[idx];
            *(uint4*)(sV + so) = gv[idx];
        }
    }
    __syncwarp();

    float e0[4] = {0.f, 0.f, 0.f, 0.f};
    float e1[4] = {0.f, 0.f, 0.f, 0.f};
#pragma unroll
    for (int kc = 0; kc < 4; kc++) {
        uint32_t a[4], b0[2], b1[2];
        ldsm4(a, sQ + (lane & 15) * 72 + kc * 16 + (lane >> 4) * 8);
        const int krow = (lane & 7);
        const int koff = kc * 16 + ((lane >> 3) & 1) * 8;
        ldsm2(b0, sK + krow * 72 + koff);
        ldsm2(b1, sK + (8 + krow) * 72 + koff);
        mma16816(e0, a, b0);
        mma16816(e1, a, b1);
    }

    const float scl = 0.03125f;
    float v00 = e0[0] * scl, v01 = e0[1] * scl, v02 = e1[0] * scl, v03 = e1[1] * scl;
    float v10 = e0[2] * scl, v11 = e0[3] * scl, v12 = e1[2] * scl, v13 = e1[3] * scl;
    float m0 = fmaxf(fmaxf(v00, v01), fmaxf(v02, v03));
    float m1 = fmaxf(fmaxf(v10, v11), fmaxf(v12, v13));
    m0 = fmaxf(m0, __shfl_xor_sync(0xffffffffu, m0, 1));
    m0 = fmaxf(m0, __shfl_xor_sync(0xffffffffu, m0, 2));
    m1 = fmaxf(m1, __shfl_xor_sync(0xffffffffu, m1, 1));
    m1 = fmaxf(m1, __shfl_xor_sync(0xffffffffu, m1, 2));
    v00 = __expf(v00 - m0); v01 = __expf(v01 - m0); v02 = __expf(v02 - m0); v03 = __expf(v03 - m0);
    v10 = __expf(v10 - m1); v11 = __expf(v11 - m1); v12 = __expf(v12 - m1); v13 = __expf(v13 - m1);
    float s0 = v00 + v01 + v02 + v03;
    float s1 = v10 + v11 + v12 + v13;
    s0 += __shfl_xor_sync(0xffffffffu, s0, 1); s0 += __shfl_xor_sync(0xffffffffu, s0, 2);
    s1 += __shfl_xor_sync(0xffffffffu, s1, 1); s1 += __shfl_xor_sync(0xffffffffu, s1, 2);
    const float i0 = 1.0f / s0, i1 = 1.0f / s1;

    uint32_t pa[4];
    __half2 h;
    h = __floats2half2_rn(v00 * i0, v01 * i0); pa[0] = *(const uint32_t*)&h;
    h = __floats2half2_rn(v10 * i1, v11 * i1); pa[1] = *(const uint32_t*)&h;
    h = __floats2half2_rn(v02 * i0, v03 * i0); pa[2] = *(const uint32_t*)&h;
    h = __floats2half2_rn(v12 * i1, v13 * i1); pa[3] = *(const uint32_t*)&h;

    const int r  = lane >> 2;
    const int t  = lane & 3;
    const int li = l & 15;
    const int lh = l >> 4;
    const int vrow = (lane & 7) + ((lane >> 3) & 1) * 8;
    const size_t rbase0 = ((size_t)n * LSEQ + r * 128 + lh) * EMB + li * 64;
    const size_t rbase1 = ((size_t)n * LSEQ + (r + 8) * 128 + lh) * EMB + li * 64;
#pragma unroll
    for (int nb = 0; nb < 8; nb++) {
        uint32_t b[2];
        ldsm2t(b, sV + vrow * 72 + nb * 8);
        float c[4] = {0.f, 0.f, 0.f, 0.f};
        mma16816(c, pa, b);
        const int d = nb * 8 + 2 * t;
        __half2 o0 = __floats2half2_rn(c[0], c[1]);
        __half2 o1 = __floats2half2_rn(c[2], c[3]);
        *(__half2*)(o + rbase0 + d) = o0;
        *(__half2*)(o + rbase1 + d) = o1;
    }
}

// ---------------------------------------------------------------------------
extern "C" void kernel_launch(void* const* d_in, const int* in_sizes, int n_in,
                              void* d_out, int out_size)
{
    const float* x  = (const float*)d_in[0];
    const float* Wv = (const float*)d_in[1];
    const float* Wk = (const float*)d_in[2];
    const float* Wq = (const float*)d_in[3];
    const float* Wo = (const float*)d_in[4];
    const float* bo = (const float*)d_in[5];
    float* out = (float*)d_out;

    void *pxh, *pwqkv, *pwo, *pq, *pk, *pv, *pa;
    cudaGetSymbolAddress(&pxh, g_xh);
    cudaGetSymbolAddress(&pwqkv, g_wqkv);
    cudaGetSymbolAddress(&pwo, g_wo);
    cudaGetSymbolAddress(&pq, g_q);
    cudaGetSymbolAddress(&pk, g_k);
    cudaGetSymbolAddress(&pv, g_v);
    cudaGetSymbolAddress(&pa, g_att);
    __half* xh    = (__half*)pxh;
    __half* wqkv  = (__half*)pwqkv;
    __half* wo    = (__half*)pwo;
    __half* qb = (__half*)pq;
    __half* kb = (__half*)pk;
    __half* vb = (__half*)pv;
    __half* ab = (__half*)pa;

    cudaFuncSetAttribute(gemm_qkv_k, cudaFuncAttributeMaxDynamicSharedMemorySize, G_SMEM);
    cudaFuncSetAttribute(gemm_out_k, cudaFuncAttributeMaxDynamicSharedMemorySize, G_SMEM);

    // 1) conversions
    const int xn8 = MTOT * EMB / 8;
    cvt_f2h<<<(xn8 + 255) / 256, 256>>>(x, xh, xn8);
    const int wn8 = EMB * EMB / 8;
    cvt_w4<<<dim3((wn8 + 255) / 256, 4), 256>>>(Wq, Wk, Wv, Wo, wqkv, wo, wn8);

    // 2) fused QKV projection: [16384,1024] @ [1024,3072]
    gemm_qkv_k<<<dim3(3 * EMB / 128, MTOT / 128), 128, G_SMEM>>>(xh, wqkv, qb, kb, vb);

    // 3) per-token head attention (scrambled fp16 output)
    attn_mma<<<MTOT / 4, 128>>>(qb, kb, vb, ab);

    // 4) output projection + bias (fp32 out, coalesced staged stores)
    gemm_out_k<<<dim3(EMB / 128, MTOT / 128), 128, G_SMEM>>>(ab, wo, out, bo);
}

// round 16
// speedup vs baseline: 1.0249x; 1.0082x over previous
#include <cuda_runtime.h>
#include <cuda_fp16.h>
#include <cstdint>

#define MTOT 16384
#define EMB  1024
#define LSEQ 2048

// ---------------- scratch (allocation-free rule) ----------------
__device__ __half g_xh[MTOT * EMB];          // fp16 x
__device__ __half g_wqkv[EMB * 3 * EMB];     // fp16 [K][Wq|Wk|Wv] (ldb=3072)
__device__ __half g_wo[EMB * EMB];           // fp16 Wo
__device__ __half g_q[MTOT * EMB];
__device__ __half g_k[MTOT * EMB];
__device__ __half g_v[MTOT * EMB];
__device__ __half g_att[MTOT * EMB];         // scrambled attention output

// ---------------- GEMM config: 128x128 CTA tile, KC=64, 3 stages -----------
#define GKC 64
#define NKT (EMB / GKC)            // 16
#define A_LDH 72                   // halves per A smem row (64 + 8 pad)
#define B_LDH 136                  // halves per B smem row (128 + 8 pad)
#define A_STB (128 * A_LDH * 2)    // 18432
#define B_STB (GKC * B_LDH * 2)    // 17408
#define STG_B (A_STB + B_STB)      // 35840
#define G_SMEM (3 * STG_B)         // 107520

// ---------------- helpers ----------------
__device__ __forceinline__ void cp16(void* s, const void* g) {
    unsigned sa = (unsigned)__cvta_generic_to_shared(s);
    asm volatile("cp.async.cg.shared.global [%0], [%1], 16;\n" :: "r"(sa), "l"(g));
}
__device__ __forceinline__ void cp_commit() {
    asm volatile("cp.async.commit_group;\n" ::);
}
template<int N>
__device__ __forceinline__ void cp_wait() {
    asm volatile("cp.async.wait_group %0;\n" :: "n"(N));
}
__device__ __forceinline__ void ldsm4(uint32_t* r, const __half* p) {
    uint32_t a = (uint32_t)__cvta_generic_to_shared(p);
    asm volatile("ldmatrix.sync.aligned.m8n8.x4.shared.b16 {%0,%1,%2,%3}, [%4];"
        : "=r"(r[0]), "=r"(r[1]), "=r"(r[2]), "=r"(r[3]) : "r"(a));
}
__device__ __forceinline__ void ldsm4t(uint32_t* r, const __half* p) {
    uint32_t a = (uint32_t)__cvta_generic_to_shared(p);
    asm volatile("ldmatrix.sync.aligned.m8n8.x4.trans.shared.b16 {%0,%1,%2,%3}, [%4];"
        : "=r"(r[0]), "=r"(r[1]), "=r"(r[2]), "=r"(r[3]) : "r"(a));
}
__device__ __forceinline__ void ldsm2(uint32_t* r, const __half* p) {
    uint32_t a = (uint32_t)__cvta_generic_to_shared(p);
    asm volatile("ldmatrix.sync.aligned.m8n8.x2.shared.b16 {%0,%1}, [%2];"
        : "=r"(r[0]), "=r"(r[1]) : "r"(a));
}
__device__ __forceinline__ void ldsm2t(uint32_t* r, const __half* p) {
    uint32_t a = (uint32_t)__cvta_generic_to_shared(p);
    asm volatile("ldmatrix.sync.aligned.m8n8.x2.trans.shared.b16 {%0,%1}, [%2];"
        : "=r"(r[0]), "=r"(r[1]) : "r"(a));
}
__device__ __forceinline__ void mma16816(float* c, const uint32_t* a, const uint32_t* b) {
    asm volatile(
        "mma.sync.aligned.m16n8k16.row.col.f32.f16.f16.f32 "
        "{%0,%1,%2,%3}, {%4,%5,%6,%7}, {%8,%9}, {%0,%1,%2,%3};"
        : "+f"(c[0]), "+f"(c[1]), "+f"(c[2]), "+f"(c[3])
        : "r"(a[0]), "r"(a[1]), "r"(a[2]), "r"(a[3]), "r"(b[0]), "r"(b[1]));
}

// ---------------------------------------------------------------------------
// 128x128 raw-mma fp16 GEMM, 128 threads (4 warps of 64x64), 3-stage cp.async,
// 2 CTAs/SM, quarter-spread cp.async issue (proven R13/R14/R15 config).
// BIAS=false: half output; column block selects among H0/H1/H2 (ldb may be 3072).
// BIAS=true : float output + bias, smem-staged 128B-coalesced stores.
// ---------------------------------------------------------------------------
template<bool BIAS>
__device__ __forceinline__ void gemm_core(
    const __half* __restrict__ A, const __half* __restrict__ B, int ldb,
    __half* __restrict__ H0, __half* __restrict__ H1, __half* __restrict__ H2,
    float* __restrict__ F, const float* __restrict__ bias)
{
    extern __shared__ char smem[];
    const int tid  = threadIdx.x;
    const int warp = tid >> 5;
    const int lane = tid & 31;
    const int bm = blockIdx.y * 128;
    const int bn = blockIdx.x * 128;
    const int wm = (warp >> 1) * 64;
    const int wn = (warp & 1) * 64;

    float c[4][8][4];
#pragma unroll
    for (int i = 0; i < 4; i++)
#pragma unroll
        for (int j = 0; j < 8; j++) {
            c[i][j][0] = 0.f; c[i][j][1] = 0.f; c[i][j][2] = 0.f; c[i][j][3] = 0.f;
        }

    auto issueA = [&](int kt, int h) {
        char* st = smem + (kt % 3) * STG_B;
#pragma unroll
        for (int i = h * 4; i < h * 4 + 4; i++) {
            const int idx = tid + i * 128;
            const int row = idx >> 3, cc = idx & 7;
            cp16(st + row * (A_LDH * 2) + cc * 16,
                 A + (size_t)(bm + row) * EMB + kt * GKC + cc * 8);
        }
    };
    auto issueB = [&](int kt, int h) {
        char* stb = smem + (kt % 3) * STG_B + A_STB;
#pragma unroll
        for (int i = h * 4; i < h * 4 + 4; i++) {
            const int idx = tid + i * 128;
            const int row = idx >> 4, cc = idx & 15;
            cp16(stb + row * (B_LDH * 2) + cc * 16,
                 B + (size_t)(kt * GKC + row) * ldb + bn + cc * 8);
        }
        if (h == 1) cp_commit();
    };

    issueA(0, 0); issueA(0, 1); issueB(0, 0); issueB(0, 1);
    issueA(1, 0); issueA(1, 1); issueB(1, 0); issueB(1, 1);

    for (int kt = 0; kt < NKT; ++kt) {
        if (kt == NKT - 1) cp_wait<0>(); else cp_wait<1>();
        __syncthreads();

        const __half* sA = (const __half*)(smem + (kt % 3) * STG_B);
        const __half* sB = (const __half*)(smem + (kt % 3) * STG_B + A_STB);
        const bool more = (kt + 2 < NKT);
#pragma unroll
        for (int kk = 0; kk < 4; ++kk) {
            uint32_t a[4][4], b[8][2];
#pragma unroll
            for (int i = 0; i < 4; i++)
                ldsm4(a[i], sA + (wm + i * 16 + (lane & 15)) * A_LDH
                              + kk * 16 + (lane >> 4) * 8);
#pragma unroll
            for (int j2 = 0; j2 < 4; j2++) {
                uint32_t t[4];
                ldsm4t(t, sB + (kk * 16 + (lane & 15)) * B_LDH
                            + wn + j2 * 16 + (lane >> 4) * 8);
                b[2 * j2][0] = t[0]; b[2 * j2][1] = t[1];
                b[2 * j2 + 1][0] = t[2]; b[2 * j2 + 1][1] = t[3];
            }
#pragma unroll
            for (int i = 0; i < 4; i++)
#pragma unroll
                for (int j = 0; j < 8; j++)
                    mma16816(c[i][j], a[i], b[j]);
            if (more) {
                if (kk == 0) issueA(kt + 2, 0);
                else if (kk == 1) issueA(kt + 2, 1);
                else if (kk == 2) issueB(kt + 2, 0);
                else issueB(kt + 2, 1);
            }
        }
    }

    const int r = lane >> 2, t = lane & 3;
    if (BIAS) {
        __syncthreads();
        float* sc = (float*)smem;   // [128][132] floats
#pragma unroll
        for (int i = 0; i < 4; i++)
#pragma unroll
            for (int j = 0; j < 8; j++) {
                const int row0 = wm + i * 16 + r;
                const int col = wn + j * 8 + 2 * t;
                *(float2*)(sc + row0 * 132 + col) = make_float2(c[i][j][0], c[i][j][1]);
                *(float2*)(sc + (row0 + 8) * 132 + col) = make_float2(c[i][j][2], c[i][j][3]);
            }
        __syncthreads();
#pragma unroll
        for (int p = 0; p < 32; p++) {
            const int idx = tid + p * 128;
            const int row = idx >> 5, cf = (idx & 31) * 4;
            const float* sp = sc + row * 132 + cf;
            float4 bb = *(const float4*)(bias + bn + cf);
            float4 v;
            v.x = sp[0] + bb.x; v.y = sp[1] + bb.y;
            v.z = sp[2] + bb.z; v.w = sp[3] + bb.w;
            *(float4*)(F + (size_t)(bm + row) * EMB + bn + cf) = v;
        }
    } else {
        __syncthreads();
        __half* sc = (__half*)smem;   // [128][136] halves
#pragma unroll
        for (int i = 0; i < 4; i++)
#pragma unroll
            for (int j = 0; j < 8; j++) {
                const int row0 = wm + i * 16 + r;
                const int col = wn + j * 8 + 2 * t;
                *(__half2*)(sc + row0 * B_LDH + col) =
                    __floats2half2_rn(c[i][j][0], c[i][j][1]);
                *(__half2*)(sc + (row0 + 8) * B_LDH + col) =
                    __floats2half2_rn(c[i][j][2], c[i][j][3]);
            }
        __syncthreads();
        const int z = bn >> 10;
        __half* O = (z == 0) ? H0 : (z == 1) ? H1 : H2;
        const int bnl = bn & 1023;
#pragma unroll
        for (int i = 0; i < 16; i++) {
            const int idx = tid + i * 128;
            const int row = idx >> 4, cc = idx & 15;
            *(uint4*)(O + (size_t)(bm + row) * EMB + bnl + cc * 8) =
                *(const uint4*)(sc + row * B_LDH + cc * 8);
        }
    }
}

__global__ void __launch_bounds__(128, 2) gemm_qkv_k(
    const __half* __restrict__ A, const __half* __restrict__ W,
    __half* __restrict__ Q, __half* __restrict__ K, __half* __restrict__ V)
{
    gemm_core<false>(A, W, 3 * EMB, Q, K, V, nullptr, nullptr);
}

__global__ void __launch_bounds__(128, 2) gemm_out_k(
    const __half* __restrict__ A, const __half* __restrict__ W,
    float* __restrict__ C, const float* __restrict__ bias)
{
    gemm_core<true>(A, W, EMB, nullptr, nullptr, nullptr, C, bias);
}

// ---------------------------------------------------------------------------
// conversions
// ---------------------------------------------------------------------------
__global__ void __launch_bounds__(256) cvt_f2h(
    const float* __restrict__ in, __half* __restrict__ out, int n8)
{
    const int i = blockIdx.x * blockDim.x + threadIdx.x;
    if (i < n8) {
        float4 a = ((const float4*)in)[2 * i];
        float4 b = ((const float4*)in)[2 * i + 1];
        __half2 h0 = __floats2half2_rn(a.x, a.y);
        __half2 h1 = __floats2half2_rn(a.z, a.w);
        __half2 h2 = __floats2half2_rn(b.x, b.y);
        __half2 h3 = __floats2half2_rn(b.z, b.w);
        uint4 u;
        u.x = *(const unsigned*)&h0; u.y = *(const unsigned*)&h1;
        u.z = *(const unsigned*)&h2; u.w = *(const unsigned*)&h3;
        ((uint4*)out)[i] = u;
    }
}

// all 4 weights in one launch: z<3 -> packed [K][3072] wqkv; z=3 -> wo
__global__ void __launch_bounds__(256) cvt_w4(
    const float* __restrict__ Wq, const float* __restrict__ Wk,
    const float* __restrict__ Wv, const float* __restrict__ Wo,
    __half* __restrict__ wqkv, __half* __restrict__ wo, int n8)
{
    const int z = blockIdx.y;
    const float* in = (z == 0) ? Wq : (z == 1) ? Wk : (z == 2) ? Wv : Wo;
    const int i = blockIdx.x * blockDim.x + threadIdx.x;
    if (i < n8) {
        float4 a = ((const float4*)in)[2 * i];
        float4 b = ((const float4*)in)[2 * i + 1];
        __half2 h0 = __floats2half2_rn(a.x, a.y);
        __half2 h1 = __floats2half2_rn(a.z, a.w);
        __half2 h2 = __floats2half2_rn(b.x, b.y);
        __half2 h3 = __floats2half2_rn(b.z, b.w);
        uint4 u;
        u.x = *(const unsigned*)&h0; u.y = *(const unsigned*)&h1;
        u.z = *(const unsigned*)&h2; u.w = *(const unsigned*)&h3;
        if (z < 3) {
            const int k = i >> 7, cc = i & 127;
            *(uint4*)(wqkv + (size_t)k * (3 * EMB) + z * EMB + cc * 8) = u;
        } else {
            ((uint4*)wo)[i] = u;
        }
    }
}

// ---------------------------------------------------------------------------
// Tensor-core per-token attention (128 thr, 4 tokens/CTA, static smem).
// NEW: PV output staged through the dead Q tile, then 128B-coalesced stores.
// ---------------------------------------------------------------------------
__global__ void __launch_bounds__(128) attn_mma(
    const __half* __restrict__ q, const __half* __restrict__ k,
    const __half* __restrict__ v, __half* __restrict__ o)
{
    __shared__ __align__(16) __half sm[4][3][16 * 72];
    const int wid  = threadIdx.x >> 5;
    const int lane = threadIdx.x & 31;
    const int tok = blockIdx.x * 4 + wid;
    const int n = tok >> 11;
    const int l = tok & 2047;
    const size_t base = (size_t)tok * EMB;

    __half* sQ = sm[wid][0];
    __half* sK = sm[wid][1];
    __half* sV = sm[wid][2];

    {
        const uint4* gq = (const uint4*)(q + base);
        const uint4* gk = (const uint4*)(k + base);
        const uint4* gv = (const uint4*)(v + base);
#pragma unroll
        for (int i = 0; i < 4; i++) {
            const int idx = lane + i * 32;
            const int row = idx >> 3, c = idx & 7;
            const int so = row * 72 + c * 8;
            *(uint4*)(sQ + so) = gq[idx];
            *(uint4*)(sK + so) = gk[idx];
            *(uint4*)(sV + so) = gv[idx];
        }
    }
    __syncwarp();

    float e0[4] = {0.f, 0.f, 0.f, 0.f};
    float e1[4] = {0.f, 0.f, 0.f, 0.f};
#pragma unroll
    for (int kc = 0; kc < 4; kc++) {
        uint32_t a[4], b0[2], b1[2];
        ldsm4(a, sQ + (lane & 15) * 72 + kc * 16 + (lane >> 4) * 8);
        const int krow = (lane & 7);
        const int koff = kc * 16 + ((lane >> 3) & 1) * 8;
        ldsm2(b0, sK + krow * 72 + koff);
        ldsm2(b1, sK + (8 + krow) * 72 + koff);
        mma16816(e0, a, b0);
        mma16816(e1, a, b1);
    }

    const float scl = 0.03125f;
    float v00 = e0[0] * scl, v01 = e0[1] * scl, v02 = e1[0] * scl, v03 = e1[1] * scl;
    float v10 = e0[2] * scl, v11 = e0[3] * scl, v12 = e1[2] * scl, v13 = e1[3] * scl;
    float m0 = fmaxf(fmaxf(v00, v01), fmaxf(v02, v03));
    float m1 = fmaxf(fmaxf(v10, v11), fmaxf(v12, v13));
    m0 = fmaxf(m0, __shfl_xor_sync(0xffffffffu, m0, 1));
    m0 = fmaxf(m0, __shfl_xor_sync(0xffffffffu, m0, 2));
    m1 = fmaxf(m1, __shfl_xor_sync(0xffffffffu, m1, 1));
    m1 = fmaxf(m1, __shfl_xor_sync(0xffffffffu, m1, 2));
    v00 = __expf(v00 - m0); v01 = __expf(v01 - m0); v02 = __expf(v02 - m0); v03 = __expf(v03 - m0);
    v10 = __expf(v10 - m1); v11 = __expf(v11 - m1); v12 = __expf(v12 - m1); v13 = __expf(v13 - m1);
    float s0 = v00 + v01 + v02 + v03;
    float s1 = v10 + v11 + v12 + v13;
    s0 += __shfl_xor_sync(0xffffffffu, s0, 1); s0 += __shfl_xor_sync(0xffffffffu, s0, 2);
    s1 += __shfl_xor_sync(0xffffffffu, s1, 1); s1 += __shfl_xor_sync(0xffffffffu, s1, 2);
    const float i0 = 1.0f / s0, i1 = 1.0f / s1;

    uint32_t pa[4];
    __half2 h;
    h = __floats2half2_rn(v00 * i0, v01 * i0); pa[0] = *(const uint32_t*)&h;
    h = __floats2half2_rn(v10 * i1, v11 * i1); pa[1] = *(const uint32_t*)&h;
    h = __floats2half2_rn(v02 * i0, v03 * i0); pa[2] = *(const uint32_t*)&h;
    h = __floats2half2_rn(v12 * i1, v13 * i1); pa[3] = *(const uint32_t*)&h;

    const int r  = lane >> 2;
    const int t  = lane & 3;
    const int vrow = (lane & 7) + ((lane >> 3) & 1) * 8;

    // O = P V, staged into the (now dead) Q tile: sQ[oh][d], stride 72
#pragma unroll
    for (int nb = 0; nb < 8; nb++) {
        uint32_t b[2];
        ldsm2t(b, sV + vrow * 72 + nb * 8);
        float c[4] = {0.f, 0.f, 0.f, 0.f};
        mma16816(c, pa, b);
        const int d = nb * 8 + 2 * t;
        *(__half2*)(sQ + r * 72 + d)       = __floats2half2_rn(c[0], c[1]);
        *(__half2*)(sQ + (r + 8) * 72 + d) = __floats2half2_rn(c[2], c[3]);
    }
    __syncwarp();

    // coalesced write-out: per (token, head) a 128B contiguous chunk
    const int li = l & 15;
    const int lh = l >> 4;
    const size_t obase = ((size_t)n * LSEQ + lh) * EMB + li * 64;
#pragma unroll
    for (int it = 0; it < 4; it++) {
        const int idx = lane + it * 32;
        const int row = idx >> 3;            // head 0..15
        const int c8  = (idx & 7) * 8;       // 0..56
        *(uint4*)(o + obase + (size_t)row * 128 * EMB + c8) =
            *(const uint4*)(sQ + row * 72 + c8);
    }
}

// ---------------------------------------------------------------------------
extern "C" void kernel_launch(void* const* d_in, const int* in_sizes, int n_in,
                              void* d_out, int out_size)
{
    const float* x  = (const float*)d_in[0];
    const float* Wv = (const float*)d_in[1];
    const float* Wk = (const float*)d_in[2];
    const float* Wq = (const float*)d_in[3];
    const float* Wo = (const float*)d_in[4];
    const float* bo = (const float*)d_in[5];
    float* out = (float*)d_out;

    void *pxh, *pwqkv, *pwo, *pq, *pk, *pv, *pa;
    cudaGetSymbolAddress(&pxh, g_xh);
    cudaGetSymbolAddress(&pwqkv, g_wqkv);
    cudaGetSymbolAddress(&pwo, g_wo);
    cudaGetSymbolAddress(&pq, g_q);
    cudaGetSymbolAddress(&pk, g_k);
    cudaGetSymbolAddress(&pv, g_v);
    cudaGetSymbolAddress(&pa, g_att);
    __half* xh    = (__half*)pxh;
    __half* wqkv  = (__half*)pwqkv;
    __half* wo    = (__half*)pwo;
    __half* qb = (__half*)pq;
    __half* kb = (__half*)pk;
    __half* vb = (__half*)pv;
    __half* ab = (__half*)pa;

    cudaFuncSetAttribute(gemm_qkv_k, cudaFuncAttributeMaxDynamicSharedMemorySize, G_SMEM);
    cudaFuncSetAttribute(gemm_out_k, cudaFuncAttributeMaxDynamicSharedMemorySize, G_SMEM);

    // 1) conversions
    const int xn8 = MTOT * EMB / 8;
    cvt_f2h<<<(xn8 + 255) / 256, 256>>>(x, xh, xn8);
    const int wn8 = EMB * EMB / 8;
    cvt_w4<<<dim3((wn8 + 255) / 256, 4), 256>>>(Wq, Wk, Wv, Wo, wqkv, wo, wn8);

    // 2) fused QKV projection: [16384,1024] @ [1024,3072]
    gemm_qkv_k<<<dim3(3 * EMB / 128, MTOT / 128), 128, G_SMEM>>>(xh, wqkv, qb, kb, vb);

    // 3) per-token head attention (scrambled fp16 output, coalesced stores)
    attn_mma<<<MTOT / 4, 128>>>(qb, kb, vb, ab);

    // 4) output projection + bias (fp32 out, coalesced staged stores)
    gemm_out_k<<<dim3(EMB / 128, MTOT / 128), 128, G_SMEM>>>(ab, wo, out, bo);
}

// round 17
// speedup vs baseline: 1.0260x; 1.0011x over previous
#include <cuda_runtime.h>
#include <cuda_fp16.h>
#include <cstdint>

#define MTOT 16384
#define EMB  1024
#define LSEQ 2048

// ---------------- scratch (allocation-free rule) ----------------
__device__ __half g_xh[MTOT * EMB];          // fp16 x
__device__ __half g_wqkv[EMB * 3 * EMB];     // fp16 [K][Wq|Wk|Wv] (ldb=3072)
__device__ __half g_wo[EMB * EMB];           // fp16 Wo
__device__ __half g_q[MTOT * EMB];
__device__ __half g_k[MTOT * EMB];
__device__ __half g_v[MTOT * EMB];
__device__ __half g_att[MTOT * EMB];         // scrambled attention output

// ---------------- GEMM config: 128x128 CTA tile, KC=64, 3 stages -----------
#define GKC 64
#define NKT (EMB / GKC)            // 16
#define A_LDH 72                   // halves per A smem row (64 + 8 pad)
#define B_LDH 136                  // halves per B smem row (128 + 8 pad)
#define A_STB (128 * A_LDH * 2)    // 18432
#define B_STB (GKC * B_LDH * 2)    // 17408
#define STG_B (A_STB + B_STB)      // 35840
#define G_SMEM (3 * STG_B)         // 107520

// ---------------- helpers ----------------
__device__ __forceinline__ void cp16(void* s, const void* g) {
    unsigned sa = (unsigned)__cvta_generic_to_shared(s);
    asm volatile("cp.async.cg.shared.global [%0], [%1], 16;\n" :: "r"(sa), "l"(g));
}
// L1-caching variant: co-resident CTA (same bm strip) hits in L1.
__device__ __forceinline__ void cp16ca(void* s, const void* g) {
    unsigned sa = (unsigned)__cvta_generic_to_shared(s);
    asm volatile("cp.async.ca.shared.global [%0], [%1], 16;\n" :: "r"(sa), "l"(g));
}
__device__ __forceinline__ void cp_commit() {
    asm volatile("cp.async.commit_group;\n" ::);
}
template<int N>
__device__ __forceinline__ void cp_wait() {
    asm volatile("cp.async.wait_group %0;\n" :: "n"(N));
}
__device__ __forceinline__ void ldsm4(uint32_t* r, const __half* p) {
    uint32_t a = (uint32_t)__cvta_generic_to_shared(p);
    asm volatile("ldmatrix.sync.aligned.m8n8.x4.shared.b16 {%0,%1,%2,%3}, [%4];"
        : "=r"(r[0]), "=r"(r[1]), "=r"(r[2]), "=r"(r[3]) : "r"(a));
}
__device__ __forceinline__ void ldsm4t(uint32_t* r, const __half* p) {
    uint32_t a = (uint32_t)__cvta_generic_to_shared(p);
    asm volatile("ldmatrix.sync.aligned.m8n8.x4.trans.shared.b16 {%0,%1,%2,%3}, [%4];"
        : "=r"(r[0]), "=r"(r[1]), "=r"(r[2]), "=r"(r[3]) : "r"(a));
}
__device__ __forceinline__ void ldsm2(uint32_t* r, const __half* p) {
    uint32_t a = (uint32_t)__cvta_generic_to_shared(p);
    asm volatile("ldmatrix.sync.aligned.m8n8.x2.shared.b16 {%0,%1}, [%2];"
        : "=r"(r[0]), "=r"(r[1]) : "r"(a));
}
__device__ __forceinline__ void ldsm2t(uint32_t* r, const __half* p) {
    uint32_t a = (uint32_t)__cvta_generic_to_shared(p);
    asm volatile("ldmatrix.sync.aligned.m8n8.x2.trans.shared.b16 {%0,%1}, [%2];"
        : "=r"(r[0]), "=r"(r[1]) : "r"(a));
}
__device__ __forceinline__ void mma16816(float* c, const uint32_t* a, const uint32_t* b) {
    asm volatile(
        "mma.sync.aligned.m16n8k16.row.col.f32.f16.f16.f32 "
        "{%0,%1,%2,%3}, {%4,%5,%6,%7}, {%8,%9}, {%0,%1,%2,%3};"
        : "+f"(c[0]), "+f"(c[1]), "+f"(c[2]), "+f"(c[3])
        : "r"(a[0]), "r"(a[1]), "r"(a[2]), "r"(a[3]), "r"(b[0]), "r"(b[1]));
}

// ---------------------------------------------------------------------------
// 128x128 raw-mma fp16 GEMM, 128 threads (4 warps of 64x64), 3-stage cp.async,
// 2 CTAs/SM, quarter-spread cp.async issue. A copies use .ca (L1 reuse across
// the co-resident CTA sharing the same bm strip); B copies use .cg.
// BIAS=false: half output; column block selects among H0/H1/H2 (ldb may be 3072).
// BIAS=true : float output + bias, smem-staged 128B-coalesced stores.
// ---------------------------------------------------------------------------
template<bool BIAS>
__device__ __forceinline__ void gemm_core(
    const __half* __restrict__ A, const __half* __restrict__ B, int ldb,
    __half* __restrict__ H0, __half* __restrict__ H1, __half* __restrict__ H2,
    float* __restrict__ F, const float* __restrict__ bias)
{
    extern __shared__ char smem[];
    const int tid  = threadIdx.x;
    const int warp = tid >> 5;
    const int lane = tid & 31;
    const int bm = blockIdx.y * 128;
    const int bn = blockIdx.x * 128;
    const int wm = (warp >> 1) * 64;
    const int wn = (warp & 1) * 64;

    float c[4][8][4];
#pragma unroll
    for (int i = 0; i < 4; i++)
#pragma unroll
        for (int j = 0; j < 8; j++) {
            c[i][j][0] = 0.f; c[i][j][1] = 0.f; c[i][j][2] = 0.f; c[i][j][3] = 0.f;
        }

    auto issueA = [&](int kt, int h) {
        char* st = smem + (kt % 3) * STG_B;
#pragma unroll
        for (int i = h * 4; i < h * 4 + 4; i++) {
            const int idx = tid + i * 128;
            const int row = idx >> 3, cc = idx & 7;
            cp16ca(st + row * (A_LDH * 2) + cc * 16,
                   A + (size_t)(bm + row) * EMB + kt * GKC + cc * 8);
        }
    };
    auto issueB = [&](int kt, int h) {
        char* stb = smem + (kt % 3) * STG_B + A_STB;
#pragma unroll
        for (int i = h * 4; i < h * 4 + 4; i++) {
            const int idx = tid + i * 128;
            const int row = idx >> 4, cc = idx & 15;
            cp16(stb + row * (B_LDH * 2) + cc * 16,
                 B + (size_t)(kt * GKC + row) * ldb + bn + cc * 8);
        }
        if (h == 1) cp_commit();
    };

    issueA(0, 0); issueA(0, 1); issueB(0, 0); issueB(0, 1);
    issueA(1, 0); issueA(1, 1); issueB(1, 0); issueB(1, 1);

    for (int kt = 0; kt < NKT; ++kt) {
        if (kt == NKT - 1) cp_wait<0>(); else cp_wait<1>();
        __syncthreads();

        const __half* sA = (const __half*)(smem + (kt % 3) * STG_B);
        const __half* sB = (const __half*)(smem + (kt % 3) * STG_B + A_STB);
        const bool more = (kt + 2 < NKT);
#pragma unroll
        for (int kk = 0; kk < 4; ++kk) {
            uint32_t a[4][4], b[8][2];
#pragma unroll
            for (int i = 0; i < 4; i++)
                ldsm4(a[i], sA + (wm + i * 16 + (lane & 15)) * A_LDH
                              + kk * 16 + (lane >> 4) * 8);
#pragma unroll
            for (int j2 = 0; j2 < 4; j2++) {
                uint32_t t[4];
                ldsm4t(t, sB + (kk * 16 + (lane & 15)) * B_LDH
                            + wn + j2 * 16 + (lane >> 4) * 8);
                b[2 * j2][0] = t[0]; b[2 * j2][1] = t[1];
                b[2 * j2 + 1][0] = t[2]; b[2 * j2 + 1][1] = t[3];
            }
#pragma unroll
            for (int i = 0; i < 4; i++)
#pragma unroll
                for (int j = 0; j < 8; j++)
                    mma16816(c[i][j], a[i], b[j]);
            if (more) {
                if (kk == 0) issueA(kt + 2, 0);
                else if (kk == 1) issueA(kt + 2, 1);
                else if (kk == 2) issueB(kt + 2, 0);
                else issueB(kt + 2, 1);
            }
        }
    }

    const int r = lane >> 2, t = lane & 3;
    if (BIAS) {
        __syncthreads();
        float* sc = (float*)smem;   // [128][132] floats
#pragma unroll
        for (int i = 0; i < 4; i++)
#pragma unroll
            for (int j = 0; j < 8; j++) {
                const int row0 = wm + i * 16 + r;
                const int col = wn + j * 8 + 2 * t;
                *(float2*)(sc + row0 * 132 + col) = make_float2(c[i][j][0], c[i][j][1]);
                *(float2*)(sc + (row0 + 8) * 132 + col) = make_float2(c[i][j][2], c[i][j][3]);
            }
        __syncthreads();
#pragma unroll
        for (int p = 0; p < 32; p++) {
            const int idx = tid + p * 128;
            const int row = idx >> 5, cf = (idx & 31) * 4;
            const float* sp = sc + row * 132 + cf;
            float4 bb = *(const float4*)(bias + bn + cf);
            float4 v;
            v.x = sp[0] + bb.x; v.y = sp[1] + bb.y;
            v.z = sp[2] + bb.z; v.w = sp[3] + bb.w;
            *(float4*)(F + (size_t)(bm + row) * EMB + bn + cf) = v;
        }
    } else {
        __syncthreads();
        __half* sc = (__half*)smem;   // [128][136] halves
#pragma unroll
        for (int i = 0; i < 4; i++)
#pragma unroll
            for (int j = 0; j < 8; j++) {
                const int row0 = wm + i * 16 + r;
                const int col = wn + j * 8 + 2 * t;
                *(__half2*)(sc + row0 * B_LDH + col) =
                    __floats2half2_rn(c[i][j][0], c[i][j][1]);
                *(__half2*)(sc + (row0 + 8) * B_LDH + col) =
                    __floats2half2_rn(c[i][j][2], c[i][j][3]);
            }
        __syncthreads();
        const int z = bn >> 10;
        __half* O = (z == 0) ? H0 : (z == 1) ? H1 : H2;
        const int bnl = bn & 1023;
#pragma unroll
        for (int i = 0; i < 16; i++) {
            const int idx = tid + i * 128;
            const int row = idx >> 4, cc = idx & 15;
            *(uint4*)(O + (size_t)(bm + row) * EMB + bnl + cc * 8) =
                *(const uint4*)(sc + row * B_LDH + cc * 8);
        }
    }
}

__global__ void __launch_bounds__(128, 2) gemm_qkv_k(
    const __half* __restrict__ A, const __half* __restrict__ W,
    __half* __restrict__ Q, __half* __restrict__ K, __half* __restrict__ V)
{
    gemm_core<false>(A, W, 3 * EMB, Q, K, V, nullptr, nullptr);
}

__global__ void __launch_bounds__(128, 2) gemm_out_k(
    const __half* __restrict__ A, const __half* __restrict__ W,
    float* __restrict__ C, const float* __restrict__ bias)
{
    gemm_core<true>(A, W, EMB, nullptr, nullptr, nullptr, C, bias);
}

// ---------------------------------------------------------------------------
// conversions
// ---------------------------------------------------------------------------
__global__ void __launch_bounds__(256) cvt_f2h(
    const float* __restrict__ in, __half* __restrict__ out, int n8)
{
    const int i = blockIdx.x * blockDim.x + threadIdx.x;
    if (i < n8) {
        float4 a = ((const float4*)in)[2 * i];
        float4 b = ((const float4*)in)[2 * i + 1];
        __half2 h0 = __floats2half2_rn(a.x, a.y);
        __half2 h1 = __floats2half2_rn(a.z, a.w);
        __half2 h2 = __floats2half2_rn(b.x, b.y);
        __half2 h3 = __floats2half2_rn(b.z, b.w);
        uint4 u;
        u.x = *(const unsigned*)&h0; u.y = *(const unsigned*)&h1;
        u.z = *(const unsigned*)&h2; u.w = *(const unsigned*)&h3;
        ((uint4*)out)[i] = u;
    }
}

// all 4 weights in one launch: z<3 -> packed [K][3072] wqkv; z=3 -> wo
__global__ void __launch_bounds__(256) cvt_w4(
    const float* __restrict__ Wq, const float* __restrict__ Wk,
    const float* __restrict__ Wv, const float* __restrict__ Wo,
    __half* __restrict__ wqkv, __half* __restrict__ wo, int n8)
{
    const int z = blockIdx.y;
    const float* in = (z == 0) ? Wq : (z == 1) ? Wk : (z == 2) ? Wv : Wo;
    const int i = blockIdx.x * blockDim.x + threadIdx.x;
    if (i < n8) {
        float4 a = ((const float4*)in)[2 * i];
        float4 b = ((const float4*)in)[2 * i + 1];
        __half2 h0 = __floats2half2_rn(a.x, a.y);
        __half2 h1 = __floats2half2_rn(a.z, a.w);
        __half2 h2 = __floats2half2_rn(b.x, b.y);
        __half2 h3 = __floats2half2_rn(b.z, b.w);
        uint4 u;
        u.x = *(const unsigned*)&h0; u.y = *(const unsigned*)&h1;
        u.z = *(const unsigned*)&h2; u.w = *(const unsigned*)&h3;
        if (z < 3) {
            const int k = i >> 7, cc = i & 127;
            *(uint4*)(wqkv + (size_t)k * (3 * EMB) + z * EMB + cc * 8) = u;
        } else {
            ((uint4*)wo)[i] = u;
        }
    }
}

// ---------------------------------------------------------------------------
// Tensor-core per-token attention (128 thr, 4 tokens/CTA, static smem),
// PV output staged through the dead Q tile, 128B-coalesced stores (R16 WIN).
// ---------------------------------------------------------------------------
__global__ void __launch_bounds__(128) attn_mma(
    const __half* __restrict__ q, const __half* __restrict__ k,
    const __half* __restrict__ v, __half* __restrict__ o)
{
    __shared__ __align__(16) __half sm[4][3][16 * 72];
    const int wid  = threadIdx.x >> 5;
    const int lane = threadIdx.x & 31;
    const int tok = blockIdx.x * 4 + wid;
    const int n = tok >> 11;
    const int l = tok & 2047;
    const size_t base = (size_t)tok * EMB;

    __half* sQ = sm[wid][0];
    __half* sK = sm[wid][1];
    __half* sV = sm[wid][2];

    {
        const uint4* gq = (const uint4*)(q + base);
        const uint4* gk = (const uint4*)(k + base);
        const uint4* gv = (const uint4*)(v + base);
#pragma unroll
        for (int i = 0; i < 4; i++) {
            const int idx = lane + i * 32;
            const int row = idx >> 3, c = idx & 7;
            const int so = row * 72 + c * 8;
            *(uint4*)(sQ + so) = gq[idx];
            *(uint4*)(sK + so) = gk[idx];
            *(uint4*)(sV + so) = gv[idx];
        }
    }
    __syncwarp();

    float e0[4] = {0.f, 0.f, 0.f, 0.f};
    float e1[4] = {0.f, 0.f, 0.f, 0.f};
#pragma unroll
    for (int kc = 0; kc < 4; kc++) {
        uint32_t a[4], b0[2], b1[2];
        ldsm4(a, sQ + (lane & 15) * 72 + kc * 16 + (lane >> 4) * 8);
        const int krow = (lane & 7);
        const int koff = kc * 16 + ((lane >> 3) & 1) * 8;
        ldsm2(b0, sK + krow * 72 + koff);
        ldsm2(b1, sK + (8 + krow) * 72 + koff);
        mma16816(e0, a, b0);
        mma16816(e1, a, b1);
    }

    const float scl = 0.03125f;
    float v00 = e0[0] * scl, v01 = e0[1] * scl, v02 = e1[0] * scl, v03 = e1[1] * scl;
    float v10 = e0[2] * scl, v11 = e0[3] * scl, v12 = e1[2] * scl, v13 = e1[3] * scl;
    float m0 = fmaxf(fmaxf(v00, v01), fmaxf(v02, v03));
    float m1 = fmaxf(fmaxf(v10, v11), fmaxf(v12, v13));
    m0 = fmaxf(m0, __shfl_xor_sync(0xffffffffu, m0, 1));
    m0 = fmaxf(m0, __shfl_xor_sync(0xffffffffu, m0, 2));
    m1 = fmaxf(m1, __shfl_xor_sync(0xffffffffu, m1, 1));
    m1 = fmaxf(m1, __shfl_xor_sync(0xffffffffu, m1, 2));
    v00 = __expf(v00 - m0); v01 = __expf(v01 - m0); v02 = __expf(v02 - m0); v03 = __expf(v03 - m0);
    v10 = __expf(v10 - m1); v11 = __expf(v11 - m1); v12 = __expf(v12 - m1); v13 = __expf(v13 - m1);
    float s0 = v00 + v01 + v02 + v03;
    float s1 = v10 + v11 + v12 + v13;
    s0 += __shfl_xor_sync(0xffffffffu, s0, 1); s0 += __shfl_xor_sync(0xffffffffu, s0, 2);
    s1 += __shfl_xor_sync(0xffffffffu, s1, 1); s1 += __shfl_xor_sync(0xffffffffu, s1, 2);
    const float i0 = 1.0f / s0, i1 = 1.0f / s1;

    uint32_t pa[4];
    __half2 h;
    h = __floats2half2_rn(v00 * i0, v01 * i0); pa[0] = *(const uint32_t*)&h;
    h = __floats2half2_rn(v10 * i1, v11 * i1); pa[1] = *(const uint32_t*)&h;
    h = __floats2half2_rn(v02 * i0, v03 * i0); pa[2] = *(const uint32_t*)&h;
    h = __floats2half2_rn(v12 * i1, v13 * i1); pa[3] = *(const uint32_t*)&h;

    const int r  = lane >> 2;
    const int t  = lane & 3;
    const int vrow = (lane & 7) + ((lane >> 3) & 1) * 8;

    // O = P V, staged into the (now dead) Q tile: sQ[oh][d], stride 72
#pragma unroll
    for (int nb = 0; nb < 8; nb++) {
        uint32_t b[2];
        ldsm2t(b, sV + vrow * 72 + nb * 8);
        float c[4] = {0.f, 0.f, 0.f, 0.f};
        mma16816(c, pa, b);
        const int d = nb * 8 + 2 * t;
        *(__half2*)(sQ + r * 72 + d)       = __floats2half2_rn(c[0], c[1]);
        *(__half2*)(sQ + (r + 8) * 72 + d) = __floats2half2_rn(c[2], c[3]);
    }
    __syncwarp();

    // coalesced write-out: per (token, head) a 128B contiguous chunk
    const int li = l & 15;
    const int lh = l >> 4;
    const size_t obase = ((size_t)n * LSEQ + lh) * EMB + li * 64;
#pragma unroll
    for (int it = 0; it < 4; it++) {
        const int idx = lane + it * 32;
        const int row = idx >> 3;            // head 0..15
        const int c8  = (idx & 7) * 8;       // 0..56
        *(uint4*)(o + obase + (size_t)row * 128 * EMB + c8) =
            *(const uint4*)(sQ + row * 72 + c8);
    }
}

// ---------------------------------------------------------------------------
extern "C" void kernel_launch(void* const* d_in, const int* in_sizes, int n_in,
                              void* d_out, int out_size)
{
    const float* x  = (const float*)d_in[0];
    const float* Wv = (const float*)d_in[1];
    const float* Wk = (const float*)d_in[2];
    const float* Wq = (const float*)d_in[3];
    const float* Wo = (const float*)d_in[4];
    const float* bo = (const float*)d_in[5];
    float* out = (float*)d_out;

    void *pxh, *pwqkv, *pwo, *pq, *pk, *pv, *pa;
    cudaGetSymbolAddress(&pxh, g_xh);
    cudaGetSymbolAddress(&pwqkv, g_wqkv);
    cudaGetSymbolAddress(&pwo, g_wo);
    cudaGetSymbolAddress(&pq, g_q);
    cudaGetSymbolAddress(&pk, g_k);
    cudaGetSymbolAddress(&pv, g_v);
    cudaGetSymbolAddress(&pa, g_att);
    __half* xh    = (__half*)pxh;
    __half* wqkv  = (__half*)pwqkv;
    __half* wo    = (__half*)pwo;
    __half* qb = (__half*)pq;
    __half* kb = (__half*)pk;
    __half* vb = (__half*)pv;
    __half* ab = (__half*)pa;

    cudaFuncSetAttribute(gemm_qkv_k, cudaFuncAttributeMaxDynamicSharedMemorySize, G_SMEM);
    cudaFuncSetAttribute(gemm_out_k, cudaFuncAttributeMaxDynamicSharedMemorySize, G_SMEM);

    // 1) conversions
    const int xn8 = MTOT * EMB / 8;
    cvt_f2h<<<(xn8 + 255) / 256, 256>>>(x, xh, xn8);
    const int wn8 = EMB * EMB / 8;
    cvt_w4<<<dim3((wn8 + 255) / 256, 4), 256>>>(Wq, Wk, Wv, Wo, wqkv, wo, wn8);

    // 2) fused QKV projection: [16384,1024] @ [1024,3072]
    gemm_qkv_k<<<dim3(3 * EMB / 128, MTOT / 128), 128, G_SMEM>>>(xh, wqkv, qb, kb, vb);

    // 3) per-token head attention (scrambled fp16 output, coalesced stores)
    attn_mma<<<MTOT / 4, 128>>>(qb, kb, vb, ab);

    // 4) output projection + bias (fp32 out, coalesced staged stores)
    gemm_out_k<<<dim3(EMB / 128, MTOT / 128), 128, G_SMEM>>>(ab, wo, out, bo);
}